// round 4
// baseline (speedup 1.0000x reference)
#include <cuda_runtime.h>
#include <math.h>

typedef unsigned long long ull;

#define BB 8
#define NN 10000
#define TT 2000
#define SS 12
#define HH 128

#define MASK_COEF 1.2615662610f   // GAUSS_NORM / sqrt(0.1)

#define EPB 64          // electrons per block (256 threads, 4 per electron)
#define H1_STRIDE 65    // ull per h1 row (64 pairs + 1 pad -> conflict-free)

// ---- f32x2 packed-math helpers (sm_103a; ptxas never auto-fuses these) ----
__device__ __forceinline__ ull fma2(ull a, ull b, ull c) {
    ull d;
    asm("fma.rn.f32x2 %0, %1, %2, %3;" : "=l"(d) : "l"(a), "l"(b), "l"(c));
    return d;
}
__device__ __forceinline__ ull pack2(float lo, float hi) {
    ull d;
    asm("mov.b64 %0, {%1, %2};" : "=l"(d) : "f"(lo), "f"(hi));
    return d;
}
__device__ __forceinline__ float2 unpack2(ull v) {
    float2 r;
    asm("mov.b64 {%0, %1}, %2;" : "=f"(r.x), "=f"(r.y) : "l"(v));
    return r;
}

__global__ void zero_kernel(float* __restrict__ out, int n) {
    int i = blockIdx.x * blockDim.x + threadIdx.x;
    if (i < n) out[i] = 0.0f;
}

__global__ __launch_bounds__(256, 2)
void fused_sensor_kernel(
    const float* __restrict__ de,    // (B,N,3)
    const float* __restrict__ mask,  // (B,N)
    const float* __restrict__ W1,    // (3,H)
    const float* __restrict__ b1,    // (H)
    const float* __restrict__ W2,    // (H,H)
    const float* __restrict__ b2,    // (H)
    const float* __restrict__ W3,    // (H,S)
    const float* __restrict__ b3,    // (S)
    float* __restrict__ out)         // (B,S,T)
{
    extern __shared__ ull smem[];
    ull* w2p = smem;                    // [64][128] : (W2[2kp][j], W2[2kp+1][j])
    ull* h1s = smem + 64 * HH;          // [EPB][H1_STRIDE] : packed h1 pairs

    const int tid = threadIdx.x;
    const int el  = tid >> 2;           // local electron 0..63
    const int q   = tid & 3;            // j-group / k-slice / tick-phase role
    const int e   = blockIdx.x * EPB + el;

    // ---- stage W2 interleaved by k-pairs (coalesced global reads) ----
    for (int idx = tid; idx < 64 * HH; idx += 256) {
        int kp = idx >> 7, j = idx & 127;
        w2p[idx] = pack2(W2[(2 * kp) * HH + j], W2[(2 * kp + 1) * HH + j]);
    }

    // ---- layer 1: this thread computes k in [32q, 32q+32) for its electron ----
    const float x0 = de[3 * e + 0];
    const float x1 = de[3 * e + 1];
    const float x2 = de[3 * e + 2];
#pragma unroll
    for (int i = 0; i < 16; ++i) {
        int kp = q * 16 + i;
        int k  = kp * 2;
        float ha = fmaf(x2, W1[2 * HH + k],     fmaf(x1, W1[HH + k],     fmaf(x0, W1[k],     b1[k])));
        float hb = fmaf(x2, W1[2 * HH + k + 1], fmaf(x1, W1[HH + k + 1], fmaf(x0, W1[k + 1], b1[k + 1])));
        h1s[el * H1_STRIDE + kp] = pack2(fmaxf(ha, 0.0f), fmaxf(hb, 0.0f));
    }
    __syncthreads();

    // ---- layer 2 (f32x2 over k-pairs): thread owns j in {8p+2q, 8p+2q+1} ----
    ull acc[32];
#pragma unroll
    for (int p = 0; p < 16; ++p) {
        int j = 8 * p + 2 * q;
        acc[2 * p]     = pack2(b2[j],     0.0f);
        acc[2 * p + 1] = pack2(b2[j + 1], 0.0f);
    }
    const ull* h1row  = h1s + el * H1_STRIDE;
    const ull* w2base = w2p + 2 * q;
#pragma unroll 4
    for (int kp = 0; kp < 64; ++kp) {
        ull h = h1row[kp];                         // LDS.64, 4-lane broadcast
        const ull* w2k = w2base + kp * HH;
#pragma unroll
        for (int p = 0; p < 16; ++p) {
            ulonglong2 w = *(const ulonglong2*)(w2k + 8 * p);  // LDS.128, bank-clean
            acc[2 * p]     = fma2(h, w.x, acc[2 * p]);
            acc[2 * p + 1] = fma2(h, w.y, acc[2 * p + 1]);
        }
    }

    // ---- layer 3 (f32x2 over sensor pairs) ----
    ull accS[6];
#pragma unroll
    for (int sp = 0; sp < 6; ++sp) accS[sp] = 0ULL;
#pragma unroll
    for (int p = 0; p < 16; ++p) {
#pragma unroll
        for (int jj = 0; jj < 2; ++jj) {
            int j = 8 * p + 2 * q + jj;
            float2 a = unpack2(acc[2 * p + jj]);
            float h2 = fmaxf(a.x + a.y, 0.0f);     // merge even/odd-k partials + relu
            ull hd = pack2(h2, h2);
            const ull* w3row = (const ull*)(W3 + j * SS);   // 12 floats = 6 pairs, 8B-aligned
#pragma unroll
            for (int sp = 0; sp < 6; ++sp)
                accS[sp] = fma2(hd, w3row[sp], accS[sp]);
        }
    }

    // ---- reduce the 4 j-slices of this electron (lanes q=0..3 share e) ----
    float resp[SS];
#pragma unroll
    for (int sp = 0; sp < 6; ++sp) {
        float2 v = unpack2(accS[sp]);
        v.x += __shfl_xor_sync(0xffffffffu, v.x, 1);
        v.x += __shfl_xor_sync(0xffffffffu, v.x, 2);
        v.y += __shfl_xor_sync(0xffffffffu, v.y, 1);
        v.y += __shfl_xor_sync(0xffffffffu, v.y, 2);
        resp[2 * sp]     = v.x + b3[2 * sp];
        resp[2 * sp + 1] = v.y + b3[2 * sp + 1];
    }

    // ---- sparse Gaussian scatter: exp(-5 d^2) < 3e-20 beyond |d|=3 ----
    const float z = x2;
    const float c = mask[e] * MASK_COEF;
    int t0 = (int)ceilf(z - 3.0f);
    int t1 = (int)floorf(z + 3.0f);
    if (t0 < 0) t0 = 0;
    if (t1 > TT - 1) t1 = TT - 1;
    const int b = e / NN;
    float* ob = out + (size_t)b * SS * TT;

    for (int t = t0 + q; t <= t1; t += 4) {         // ticks split across the 4 threads
        float d = (float)t - z;
        float w = __expf(-5.0f * d * d) * c;
#pragma unroll
        for (int s = 0; s < SS; ++s)
            atomicAdd(&ob[s * TT + t], w * resp[s]);
    }
}

extern "C" void kernel_launch(void* const* d_in, const int* in_sizes, int n_in,
                              void* d_out, int out_size) {
    const float* de   = (const float*)d_in[0];
    const float* mask = (const float*)d_in[1];
    const float* W1   = (const float*)d_in[2];
    const float* b1   = (const float*)d_in[3];
    const float* W2   = (const float*)d_in[4];
    const float* b2   = (const float*)d_in[5];
    const float* W3   = (const float*)d_in[6];
    const float* b3   = (const float*)d_in[7];
    float* out = (float*)d_out;

    const int total_out = BB * SS * TT;             // 192000
    zero_kernel<<<(total_out + 255) / 256, 256>>>(out, total_out);

    const int smem_bytes = (64 * HH + EPB * H1_STRIDE) * (int)sizeof(ull);  // 98816
    cudaFuncSetAttribute(fused_sensor_kernel,
                         cudaFuncAttributeMaxDynamicSharedMemorySize, smem_bytes);

    const int blocks = (BB * NN) / EPB;             // 1250
    fused_sensor_kernel<<<blocks, 256, smem_bytes>>>(
        de, mask, W1, b1, W2, b2, W3, b3, out);
}